// round 5
// baseline (speedup 1.0000x reference)
#include <cuda_runtime.h>
#include <cuda_fp16.h>
#include <math.h>

#define BATCH 128
#define OUT   256
#define MB    8      // M branches
#define INS   512    // inner size (full K in smem, f16)
#define TI    16     // batch tile
#define TB    16     // out tile
#define KP    (INS + 8)   // pad 8 halves -> w-row LDS perfectly bank-spread

// scratch: S[i][b][j] = sum_k sigmoid(x[i,j,k]*W[b,j,k])
__device__ float g_S[BATCH * OUT * MB];

__device__ __forceinline__ unsigned tanh_h2u(__half2 v) {
    unsigned r, a = *(unsigned*)&v;
    asm("tanh.approx.f16x2 %0, %1;" : "=r"(r) : "r"(a));
    return r;
}

// One CTA = (16 i x 16 b) tile of ONE branch j, full K in f16 smem.
// sigmoid(u) = 0.5 + 0.5*tanh(u/2); x prescaled by 0.5.
// The k-reduction + f16->f32 conversion run on the TENSOR pipe:
// mma.m16n8k16 with B = all-ones sums 16 tanh values per pair per step,
// accumulating exactly in f32. XU pipe carries ONLY tanh.approx.f16x2.
__global__ __launch_bounds__(256) void dnm_main_kernel(
    const float* __restrict__ x,
    const float* __restrict__ w)
{
    __shared__ __half xs[TI][KP];
    __shared__ __half ws[TB][KP];

    const int tid  = threadIdx.x;
    const int warp = tid >> 5;        // 0..7
    const int lane = tid & 31;
    const int i0   = blockIdx.x * TI;
    const int b0   = blockIdx.y * TB;
    const int j    = blockIdx.z;      // 1024 CTAs total

    // ---- cooperative load + f32->f16 convert (x scaled by 0.5) ----
    #pragma unroll
    for (int it = 0; it < (TI * INS) / (4 * 256); ++it) {
        int idx = it * 256 + tid;
        int r = idx >> 7, c = (idx & 127) << 2;   // 128 float4 per row
        float4 v = *(const float4*)&x[((size_t)(i0 + r) * MB + j) * INS + c];
        *(__half2*)&xs[r][c]     = __floats2half2_rn(0.5f * v.x, 0.5f * v.y);
        *(__half2*)&xs[r][c + 2] = __floats2half2_rn(0.5f * v.z, 0.5f * v.w);
    }
    #pragma unroll
    for (int it = 0; it < (TB * INS) / (4 * 256); ++it) {
        int idx = it * 256 + tid;
        int r = idx >> 7, c = (idx & 127) << 2;
        float4 v = *(const float4*)&w[((size_t)(b0 + r) * MB + j) * INS + c];
        *(__half2*)&ws[r][c]     = __floats2half2_rn(v.x, v.y);
        *(__half2*)&ws[r][c + 2] = __floats2half2_rn(v.z, v.w);
    }
    __syncthreads();

    // MMA fragment mapping (m16n8k16, row.col):
    //   A rows 0-7  = (i_a, b_q) q=0..7 ; rows 8-15 = (i_b, b_q)
    //   lane: q = lane/4 (b index), kb = (lane%4)*2 (k offset)
    //   a0=(i_a,kb) a1=(i_b,kb) a2=(i_a,kb+8) a3=(i_b,kb+8)
    //   D: c0 = rowsum(i_a,b_q), c2 = rowsum(i_b,b_q)  (B all-ones)
    const int q  = lane >> 2;
    const int kb = (lane & 3) << 1;
    const __half* xra = &xs[2 * warp][0];
    const __half* xrb = &xs[2 * warp + 1][0];
    const unsigned ONES = 0x3C003C00u;   // half2(1,1)

    #pragma unroll 1
    for (int bh = 0; bh < 2; ++bh) {
        const __half* wr = &ws[bh * 8 + q][0];
        float c0 = 0.0f, c1 = 0.0f, c2 = 0.0f, c3 = 0.0f;

        #pragma unroll 8
        for (int kk = 0; kk < INS; kk += 16) {
            __half2 xa  = *(const __half2*)&xra[kk + kb];
            __half2 xa2 = *(const __half2*)&xra[kk + kb + 8];
            __half2 xb  = *(const __half2*)&xrb[kk + kb];
            __half2 xb2 = *(const __half2*)&xrb[kk + kb + 8];
            __half2 wv  = *(const __half2*)&wr[kk + kb];
            __half2 wv2 = *(const __half2*)&wr[kk + kb + 8];

            unsigned a0 = tanh_h2u(__hmul2(xa,  wv));
            unsigned a1 = tanh_h2u(__hmul2(xb,  wv));
            unsigned a2 = tanh_h2u(__hmul2(xa2, wv2));
            unsigned a3 = tanh_h2u(__hmul2(xb2, wv2));

            asm volatile(
                "mma.sync.aligned.m16n8k16.row.col.f32.f16.f16.f32 "
                "{%0,%1,%2,%3}, {%4,%5,%6,%7}, {%8,%9}, {%0,%1,%2,%3};"
                : "+f"(c0), "+f"(c1), "+f"(c2), "+f"(c3)
                : "r"(a0), "r"(a1), "r"(a2), "r"(a3), "r"(ONES), "r"(ONES));
        }

        // c0 = sum_k tanh for (i_a, b), c2 for (i_b, b); S = 256 + 0.5*sum
        if ((lane & 3) == 0) {
            int bg = b0 + bh * 8 + q;
            g_S[((size_t)(i0 + 2 * warp)     * OUT + bg) * MB + j] = fmaf(0.5f, c0, 256.0f);
            g_S[((size_t)(i0 + 2 * warp + 1) * OUT + bg) * MB + j] = fmaf(0.5f, c2, 256.0f);
        }
    }
}

// Per-row normalize with fused product-of-branches.
// zn = v/total has mean exactly 1/256; ddof=1 var = (sum zn^2 - 1/256)/255.
__global__ __launch_bounds__(OUT) void dnm_norm_kernel(float* __restrict__ out)
{
    const int i = blockIdx.x;
    const int b = threadIdx.x;

    const float* sp = &g_S[((size_t)i * OUT + b) * MB];
    float4 a = *(const float4*)sp;
    float4 c = *(const float4*)(sp + 4);
    float v = ((a.x * a.y) * (a.z * a.w)) * ((c.x * c.y) * (c.z * c.w));

    // v ~ 256^8 = 2^64 -> scale before squaring (stats are scale-invariant)
    float vs = v * 0x1p-64f;

    float s1 = vs, s2 = vs * vs;
    #pragma unroll
    for (int off = 16; off > 0; off >>= 1) {
        s1 += __shfl_xor_sync(0xffffffffu, s1, off);
        s2 += __shfl_xor_sync(0xffffffffu, s2, off);
    }
    __shared__ float r1[8], r2[8];
    if ((b & 31) == 0) { r1[b >> 5] = s1; r2[b >> 5] = s2; }
    __syncthreads();

    float total = 0.0f, sq = 0.0f;
    #pragma unroll
    for (int q = 0; q < 8; ++q) { total += r1[q]; sq += r2[q]; }

    float inv = 1.0f / total;
    float zn  = vs * inv;
    float var = (sq * inv * inv - 1.0f / 256.0f) * (1.0f / 255.0f);
    out[(size_t)i * OUT + b] = (zn - 1.0f / 256.0f) * rsqrtf(var);
}

extern "C" void kernel_launch(void* const* d_in, const int* in_sizes, int n_in,
                              void* d_out, int out_size)
{
    const float* x = (const float*)d_in[0];   // (128, 8, 512)
    const float* w = (const float*)d_in[1];   // (256, 8, 512)
    float* z = (float*)d_out;                 // (128, 256)

    dim3 grid(BATCH / TI, OUT / TB, MB);      // (8, 16, 8) = 1024 CTAs
    dnm_main_kernel<<<grid, 256>>>(x, w);
    dnm_norm_kernel<<<BATCH, OUT>>>(z);
}